// round 14
// baseline (speedup 1.0000x reference)
#include <cuda_runtime.h>
#include <cuda_fp16.h>

#define N_VN    24576
#define D_V     4
#define D_C     8
#define E_EDGES (N_VN * D_V)     // 98304
#define M_CN    (E_EDGES / D_C)  // 12288
#define BSZ     64
#define CLIPV   20.0f
#define EPSV    1e-12f
#define S15     3.0517578125e-05f   // 2^-15
#define S14     6.103515625e-05f    // 2^-14
#define LN2F    0.69314718056f
#define MAXIT   12
#define SUMH2   (N_VN * 32)       // half2 units per sum buffer (3MB)

// ---------------- scratch (device globals: allocation-free) ----------------
__device__ __half  g_llrT[N_VN * BSZ];           // llr transposed [vn][b], fp16
__device__ __half2 g_c2v[E_EDGES * 32];          // CN-major [edge][b/2], fp16
__device__ __half2 g_sum[(MAXIT + 1) * SUMH2];   // per-iter VN sums [buf][vn][b/2]

__device__ __forceinline__ float clipf(float v, float lo, float hi) {
    return fminf(fmaxf(v, lo), hi);
}
__device__ __forceinline__ __half2 h2(unsigned u) {
    return *reinterpret_cast<__half2*>(&u);
}
__device__ __forceinline__ float copysgn(float mag, float s) {
    return __int_as_float((__float_as_int(mag) & 0x7fffffff) |
                          (__float_as_int(s) & 0x80000000));
}

// ------------- setup: transpose llr (fp32 [b][n] -> fp16 [n][b]) ------------
__global__ void k_setup(const float* __restrict__ in) {
    __shared__ float tile[BSZ * 33];
    int n0 = blockIdx.x * 32;
    int t = threadIdx.x;
#pragma unroll
    for (int k = 0; k < 8; k++) {       // load 32n x 64b tile (b-major source)
        int idx = t + k * 256;
        int nn = idx & 31, b = idx >> 5;
        tile[b * 33 + nn] = in[b * N_VN + n0 + nn];
    }
    __syncthreads();
#pragma unroll
    for (int k = 0; k < 8; k++) {
        int idx = t + k * 256;
        int b = idx & 63, nn = idx >> 6;
        g_llrT[(n0 + nn) * BSZ + b] = __float2half(tile[b * 33 + nn]);
    }
}

// ------------- zero the REDG target buffers sum[1..iters] ------------------
__global__ void k_zero(int n4) {        // n4 = uint4 count to zero
    uint4* p = reinterpret_cast<uint4*>(g_sum + SUMH2);   // skip buffer 0
    int stride = gridDim.x * blockDim.x;
    for (int i = blockIdx.x * blockDim.x + threadIdx.x; i < n4; i += stride)
        p[i] = make_uint4(0u, 0u, 0u, 0u);
}

// ------------- fused per-iteration kernel ----------------------------------
// One thread = one CN x 4 batch lanes (16 threads per CN).
//   belief_v2c = llr*chw + sum[it][vn] - own_c2v   (3 loads, no plane gather)
//   own c2v is CN-major -> sequential read AND write
//   new c2v REDG-accumulated into sum[it+1][vn] (fp16 atomic, no return)
// Division-free CN math (log2 domain), 3 MUFU per edge-lane.
__global__ void __launch_bounds__(256, 2) k_cn(const float* __restrict__ cn_w,
                                               const float* __restrict__ ch_w,
                                               const int* __restrict__ e2v,
                                               int it) {
    int idx = blockIdx.x * blockDim.x + threadIdx.x;   // M_CN * 16
    int cn = idx >> 4, qq = idx & 15;
    float cw  = __ldg(&cn_w[it]);
    float chw = __ldg(&ch_w[it]);
    const float oc = 0.999999f;
    float satl2 = __log2f(__fdividef(1.0f + oc, (1.0f - oc) + EPSV));
    float cwl2  = cw * LN2F;
    const uint2* sr = reinterpret_cast<const uint2*>(g_sum + it * SUMH2);
    __half2*     sw = g_sum + (it + 1) * SUMH2;
    const uint2* lp = reinterpret_cast<const uint2*>(g_llrT);
    uint2*       cp = reinterpret_cast<uint2*>(g_c2v);
    int obase = cn * 128 + qq;          // own uint2 index for edge j: + j*16

    // prefetch the 8 VN ids of this CN (2x LDG.128; e2v row is 32B-aligned)
    const int4* ev = reinterpret_cast<const int4*>(e2v) + cn * 2;
    int4 vA = __ldg(ev);
    int4 vB = __ldg(ev + 1);
    int vns[D_C] = {vA.x, vA.y, vA.z, vA.w, vB.x, vB.y, vB.z, vB.w};

    float4 a[D_C], s[D_C];
    float4 B = make_float4(1.f, 1.f, 1.f, 1.f);
#pragma unroll
    for (int j = 0; j < D_C; j++) {
        int ro = vns[j] * 16 + qq;
        uint2 ul = lp[ro];
        float2 L0 = __half22float2(h2(ul.x));
        float2 L1 = __half22float2(h2(ul.y));
        float vx, vy, vz, vw;
        if (it == 0) {                  // uniform branch: no sums/own yet
            vx = clipf(L0.x * chw, -CLIPV, CLIPV);
            vy = clipf(L0.y * chw, -CLIPV, CLIPV);
            vz = clipf(L1.x * chw, -CLIPV, CLIPV);
            vw = clipf(L1.y * chw, -CLIPV, CLIPV);
        } else {
            uint2 us = sr[ro];
            uint2 uo = cp[obase + j * 16];
            float2 S0 = __half22float2(h2(us.x));
            float2 S1 = __half22float2(h2(us.y));
            float2 o0 = __half22float2(h2(uo.x));
            float2 o1 = __half22float2(h2(uo.y));
            vx = clipf(fmaf(L0.x, chw, S0.x) - o0.x, -CLIPV, CLIPV);
            vy = clipf(fmaf(L0.y, chw, S0.y) - o0.y, -CLIPV, CLIPV);
            vz = clipf(fmaf(L1.x, chw, S1.x) - o1.x, -CLIPV, CLIPV);
            vw = clipf(fmaf(L1.y, chw, S1.y) - o1.y, -CLIPV, CLIPV);
        }
        float ex = __expf(vx), ey = __expf(vy), ez = __expf(vz), ew = __expf(vw);
        a[j].x = fmaf(ex, S15, -S15);
        a[j].y = fmaf(ey, S15, -S15);
        a[j].z = fmaf(ez, S15, -S15);
        a[j].w = fmaf(ew, S15, -S15);
        B.x *= fmaf(ex, S15, S15);
        B.y *= fmaf(ey, S15, S15);
        B.z *= fmaf(ez, S15, S15);
        B.w *= fmaf(ew, S15, S15);
    }

    // suffix products of a
    float4 S = make_float4(1.f, 1.f, 1.f, 1.f);
#pragma unroll
    for (int j = D_C - 1; j >= 0; j--) {
        s[j] = S;
        S.x *= a[j].x; S.y *= a[j].y; S.z *= a[j].z; S.w *= a[j].w;
    }

    // output pass: C = prefix*suffix*b; u = (log2(B+C)-log2(B-C))*ln2*cw
    float4 P = make_float4(1.f, 1.f, 1.f, 1.f);
#pragma unroll
    for (int j = 0; j < D_C; j++) {
        float bx = a[j].x + S14, by = a[j].y + S14;
        float bz = a[j].z + S14, bw = a[j].w + S14;
        float Cx = (P.x * s[j].x) * bx;
        float Cy = (P.y * s[j].y) * by;
        float Cz = (P.z * s[j].z) * bz;
        float Cw = (P.w * s[j].w) * bw;
        float dx = __log2f(B.x + Cx) - __log2f(B.x - Cx);
        float dy = __log2f(B.y + Cy) - __log2f(B.y - Cy);
        float dz = __log2f(B.z + Cz) - __log2f(B.z - Cz);
        float dw = __log2f(B.w + Cw) - __log2f(B.w - Cw);
        dx = (fabsf(Cx) > oc * B.x) ? copysgn(satl2, Cx) : dx;
        dy = (fabsf(Cy) > oc * B.y) ? copysgn(satl2, Cy) : dy;
        dz = (fabsf(Cz) > oc * B.z) ? copysgn(satl2, Cz) : dz;
        dw = (fabsf(Cw) > oc * B.w) ? copysgn(satl2, Cw) : dw;
        float cx = clipf(dx * cwl2, -CLIPV, CLIPV);
        float cy = clipf(dy * cwl2, -CLIPV, CLIPV);
        float cz = clipf(dz * cwl2, -CLIPV, CLIPV);
        float cv = clipf(dw * cwl2, -CLIPV, CLIPV);
        __half2 ha = __floats2half2_rn(cx, cy);
        __half2 hb = __floats2half2_rn(cz, cv);
        uint2 o;
        o.x = *reinterpret_cast<unsigned*>(&ha);
        o.y = *reinterpret_cast<unsigned*>(&hb);
        cp[obase + j * 16] = o;                        // own store (sequential)
        __half2* dst = sw + vns[j] * 32 + qq * 2;      // VN-sum accumulate
        atomicAdd(dst, ha);
        atomicAdd(dst + 1, hb);
        P.x *= a[j].x; P.y *= a[j].y; P.z *= a[j].z; P.w *= a[j].w;
    }
}

// ---------------- final: dec = llr_in + sum[iters], transposed out ---------
__global__ void k_out(const float* __restrict__ in, float* __restrict__ out,
                      int iters) {
    __shared__ float tile[BSZ * 33];
    const __half* sv = reinterpret_cast<const __half*>(g_sum + iters * SUMH2);
    int n0 = blockIdx.x * 32;
    int t = threadIdx.x;
#pragma unroll
    for (int k = 0; k < 8; k++) {       // b-fast mapping: coalesced sum reads
        int idx = t + k * 256;
        int b = idx & 63, nn = idx >> 6;
        tile[b * 33 + nn] = __half2float(sv[(n0 + nn) * BSZ + b]);
    }
    __syncthreads();
#pragma unroll
    for (int k = 0; k < 8; k++) {       // n-fast mapping: coalesced out writes
        int idx = t + k * 256;
        int nn = idx & 31, b = idx >> 5;
        out[b * N_VN + n0 + nn] = in[b * N_VN + n0 + nn] + tile[b * 33 + nn];
    }
}

// ---------------- launch ----------------
extern "C" void kernel_launch(void* const* d_in, const int* in_sizes, int n_in,
                              void* d_out, int out_size) {
    const float* llr  = (const float*)d_in[0];
    const float* cn_w = (const float*)d_in[1];
    const float* ch_w = (const float*)d_in[2];
    const int*   e2v  = (const int*)d_in[3];
    int iters = in_sizes[1];   // cn_weight length
    if (iters > MAXIT) iters = MAXIT;

    k_setup<<<N_VN / 32, 256>>>(llr);
    k_zero<<<1024, 256>>>(iters * (SUMH2 / 4));

    for (int it = 0; it < iters; it++)
        k_cn<<<(M_CN * 16) / 256, 256>>>(cn_w, ch_w, e2v, it);

    k_out<<<N_VN / 32, 256>>>(llr, (float*)d_out, iters);
}

// round 15
// speedup vs baseline: 1.5917x; 1.5917x over previous
#include <cuda_runtime.h>
#include <cuda_fp16.h>

#define N_VN    24576
#define D_V     4
#define D_C     8
#define E_EDGES (N_VN * D_V)     // 98304
#define M_CN    (E_EDGES / D_C)  // 12288
#define BSZ     64
#define CLIPV   20.0f
#define EPSV    1e-12f
#define S15     3.0517578125e-05f   // 2^-15
#define S14     6.103515625e-05f    // 2^-14
#define LN2F    0.69314718056f

#define PLANEU2 (N_VN * 16)      // uint2 (=4 halves) elements per plane
#define BUFU2   (4 * PLANEU2)    // uint2 elements per buffer (4 slots)

// ---------------- scratch (device globals: allocation-free) ----------------
__device__ __half g_llrT[N_VN * BSZ];              // llr transposed [vn][b], fp16
__device__ uint2 g_c2v[2 * BUFU2];                 // double-buffered [buf][slot][vn][b/4]
__device__ int   g_vn_edges[N_VN * D_V];           // vn -> its 4 edges (sorted)
__device__ __align__(16) int2 g_eidx[E_EDGES];     // edge -> {vn*16, slot*PLANEU2+vn*16}
__device__ int   g_vn_cnt[N_VN];

__device__ __forceinline__ float clipf(float v, float lo, float hi) {
    return fminf(fmaxf(v, lo), hi);
}
__device__ __forceinline__ __half2 h2(unsigned u) {
    return *reinterpret_cast<__half2*>(&u);
}
__device__ __forceinline__ float copysgn(float mag, float s) {
    return __int_as_float((__float_as_int(mag) & 0x7fffffff) |
                          (__float_as_int(s) & 0x80000000));
}

// ------------- setup: transpose llr fp32 [b][n] -> fp16 [n][b] -------------
__global__ void k_setup(const float* __restrict__ in) {
    __shared__ float tile[BSZ * 33];
    int n0 = blockIdx.x * 32;
    int t = threadIdx.x;
#pragma unroll
    for (int k = 0; k < 8; k++) {       // load 32n x 64b tile (b-major source)
        int idx = t + k * 256;
        int nn = idx & 31, b = idx >> 5;
        tile[b * 33 + nn] = in[b * N_VN + n0 + nn];
    }
    if (t < 32) g_vn_cnt[n0 + t] = 0;
    __syncthreads();
#pragma unroll
    for (int k = 0; k < 8; k++) {
        int idx = t + k * 256;
        int b = idx & 63, nn = idx >> 6;
        g_llrT[(n0 + nn) * BSZ + b] = __float2half(tile[b * 33 + nn]);
    }
}

__global__ void k_build_inverse(const int* __restrict__ e2v) {
    int e = blockIdx.x * blockDim.x + threadIdx.x;
    if (e < E_EDGES) {
        int n = e2v[e];
        int pos = atomicAdd(&g_vn_cnt[n], 1);
        g_vn_edges[n * D_V + pos] = e;
    }
}

// sort each VN's 4 edges ascending (deterministic slots); emit index table
__global__ void k_sort4() {
    int n = blockIdx.x * blockDim.x + threadIdx.x;
    if (n >= N_VN) return;
    int* p = &g_vn_edges[n * 4];
    int a = p[0], b = p[1], c = p[2], d = p[3], x;
    if (a > b) { x = a; a = b; b = x; }
    if (c > d) { x = c; c = d; d = x; }
    if (a > c) { x = a; a = c; c = x; }
    if (b > d) { x = b; b = d; d = x; }
    if (b > c) { x = b; b = c; c = x; }
    p[0] = a; p[1] = b; p[2] = c; p[3] = d;
    int ro = n * 16;
    g_eidx[a] = make_int2(ro, 0 * PLANEU2 + ro);
    g_eidx[b] = make_int2(ro, 1 * PLANEU2 + ro);
    g_eidx[c] = make_int2(ro, 2 * PLANEU2 + ro);
    g_eidx[d] = make_int2(ro, 3 * PLANEU2 + ro);
}

// shared CN tail: from scaled tanh-numerators a[] and denominator product B,
// compute all 8 outputs and store to wp. (log2-domain, division-free)
__device__ __forceinline__ void cn_tail(float4* a, const int* wfs, float4 B,
                                        float satl2, float cwl2, float oc,
                                        uint2* wp) {
    float4 s[D_C];
    float4 S = make_float4(1.f, 1.f, 1.f, 1.f);
#pragma unroll
    for (int j = D_C - 1; j >= 0; j--) {
        s[j] = S;
        S.x *= a[j].x; S.y *= a[j].y; S.z *= a[j].z; S.w *= a[j].w;
    }
    float4 P = make_float4(1.f, 1.f, 1.f, 1.f);
#pragma unroll
    for (int j = 0; j < D_C; j++) {
        float bx = a[j].x + S14, by = a[j].y + S14;
        float bz = a[j].z + S14, bw = a[j].w + S14;
        float Cx = (P.x * s[j].x) * bx;
        float Cy = (P.y * s[j].y) * by;
        float Cz = (P.z * s[j].z) * bz;
        float Cw = (P.w * s[j].w) * bw;
        float dx = __log2f(B.x + Cx) - __log2f(B.x - Cx);
        float dy = __log2f(B.y + Cy) - __log2f(B.y - Cy);
        float dz = __log2f(B.z + Cz) - __log2f(B.z - Cz);
        float dw = __log2f(B.w + Cw) - __log2f(B.w - Cw);
        dx = (fabsf(Cx) > oc * B.x) ? copysgn(satl2, Cx) : dx;
        dy = (fabsf(Cy) > oc * B.y) ? copysgn(satl2, Cy) : dy;
        dz = (fabsf(Cz) > oc * B.z) ? copysgn(satl2, Cz) : dz;
        dw = (fabsf(Cw) > oc * B.w) ? copysgn(satl2, Cw) : dw;
        float cx = clipf(dx * cwl2, -CLIPV, CLIPV);
        float cy = clipf(dy * cwl2, -CLIPV, CLIPV);
        float cz = clipf(dz * cwl2, -CLIPV, CLIPV);
        float cv = clipf(dw * cwl2, -CLIPV, CLIPV);
        __half2 ha = __floats2half2_rn(cx, cy);
        __half2 hb = __floats2half2_rn(cz, cv);
        uint2 o;
        o.x = *reinterpret_cast<unsigned*>(&ha);
        o.y = *reinterpret_cast<unsigned*>(&hb);
        wp[wfs[j]] = o;
        P.x *= a[j].x; P.y *= a[j].y; P.z *= a[j].z; P.w *= a[j].w;
    }
}

// ------------- iteration 0: c2v == 0, no c2v reads at all ------------------
__global__ void __launch_bounds__(256, 2) k_cn0(const float* __restrict__ cn_w,
                                                const float* __restrict__ ch_w) {
    int idx = blockIdx.x * blockDim.x + threadIdx.x;   // M_CN * 16
    int cn = idx >> 4, qq = idx & 15;
    float cw  = __ldg(&cn_w[0]);
    float chw = __ldg(&ch_w[0]);
    const float oc = 0.999999f;
    float satl2 = __log2f(__fdividef(1.0f + oc, (1.0f - oc) + EPSV));
    float cwl2  = cw * LN2F;
    uint2* wp = g_c2v + BUFU2;          // write buffer 1
    const uint2* lp = reinterpret_cast<const uint2*>(g_llrT);

    const int4* ei4 = reinterpret_cast<const int4*>(g_eidx + cn * D_C);
    int4 e01 = __ldg(ei4 + 0);
    int4 e23 = __ldg(ei4 + 1);
    int4 e45 = __ldg(ei4 + 2);
    int4 e67 = __ldg(ei4 + 3);
    int ros[D_C] = {e01.x, e01.z, e23.x, e23.z, e45.x, e45.z, e67.x, e67.z};
    int wfs[D_C] = {e01.y, e01.w, e23.y, e23.w, e45.y, e45.w, e67.y, e67.w};

    float4 a[D_C];
    float4 B = make_float4(1.f, 1.f, 1.f, 1.f);
#pragma unroll
    for (int j = 0; j < D_C; j++) {
        int ro = ros[j] + qq;
        wfs[j] += qq;
        uint2 ul = lp[ro];
        float2 L0 = __half22float2(h2(ul.x));
        float2 L1 = __half22float2(h2(ul.y));
        float vx = clipf(L0.x * chw, -CLIPV, CLIPV);
        float vy = clipf(L0.y * chw, -CLIPV, CLIPV);
        float vz = clipf(L1.x * chw, -CLIPV, CLIPV);
        float vw = clipf(L1.y * chw, -CLIPV, CLIPV);
        float ex = __expf(vx), ey = __expf(vy), ez = __expf(vz), ew = __expf(vw);
        a[j].x = fmaf(ex, S15, -S15);
        a[j].y = fmaf(ey, S15, -S15);
        a[j].z = fmaf(ez, S15, -S15);
        a[j].w = fmaf(ew, S15, -S15);
        B.x *= fmaf(ex, S15, S15);
        B.y *= fmaf(ey, S15, S15);
        B.z *= fmaf(ez, S15, S15);
        B.w *= fmaf(ew, S15, S15);
    }
    cn_tail(a, wfs, B, satl2, cwl2, oc, wp);
}

// ------------- main per-iteration kernel (it >= 1) -------------------------
// One thread = one CN x 4 batch lanes. Reads buffer rb, writes rb^1.
__global__ void __launch_bounds__(256, 2) k_cn(const float* __restrict__ cn_w,
                                               const float* __restrict__ ch_w,
                                               int it, int rb) {
    int idx = blockIdx.x * blockDim.x + threadIdx.x;   // M_CN * 16
    int cn = idx >> 4, qq = idx & 15;
    float cw  = __ldg(&cn_w[it]);
    float chw = __ldg(&ch_w[it]);
    const float oc = 0.999999f;
    float satl2 = __log2f(__fdividef(1.0f + oc, (1.0f - oc) + EPSV));
    float cwl2  = cw * LN2F;
    const uint2* rp = g_c2v + rb * BUFU2;
    uint2*       wp = g_c2v + (rb ^ 1) * BUFU2;
    const uint2* lp = reinterpret_cast<const uint2*>(g_llrT);

    const int4* ei4 = reinterpret_cast<const int4*>(g_eidx + cn * D_C);
    int4 e01 = __ldg(ei4 + 0);
    int4 e23 = __ldg(ei4 + 1);
    int4 e45 = __ldg(ei4 + 2);
    int4 e67 = __ldg(ei4 + 3);
    int ros[D_C] = {e01.x, e01.z, e23.x, e23.z, e45.x, e45.z, e67.x, e67.z};
    int wfs[D_C] = {e01.y, e01.w, e23.y, e23.w, e45.y, e45.w, e67.y, e67.w};

    float4 a[D_C];
    float4 B = make_float4(1.f, 1.f, 1.f, 1.f);
#pragma unroll
    for (int j = 0; j < D_C; j++) {
        int ro = ros[j] + qq;
        int wf = wfs[j] + qq;
        wfs[j] = wf;
        uint2 u0 = rp[ro];
        uint2 u1 = rp[ro + PLANEU2];
        uint2 u2 = rp[ro + 2 * PLANEU2];
        uint2 u3 = rp[ro + 3 * PLANEU2];
        uint2 uo = rp[wf];                         // own c2v (no slot selects)
        uint2 ul = lp[ro];
        __half2 sA = __hadd2(__hadd2(h2(u0.x), h2(u1.x)), __hadd2(h2(u2.x), h2(u3.x)));
        __half2 sB = __hadd2(__hadd2(h2(u0.y), h2(u1.y)), __hadd2(h2(u2.y), h2(u3.y)));
        float2 sa = __half22float2(sA), sb = __half22float2(sB);
        float2 oa = __half22float2(h2(uo.x)), ob = __half22float2(h2(uo.y));
        float2 L0 = __half22float2(h2(ul.x));
        float2 L1 = __half22float2(h2(ul.y));
        float vx = clipf(fmaf(L0.x, chw, sa.x) - oa.x, -CLIPV, CLIPV);
        float vy = clipf(fmaf(L0.y, chw, sa.y) - oa.y, -CLIPV, CLIPV);
        float vz = clipf(fmaf(L1.x, chw, sb.x) - ob.x, -CLIPV, CLIPV);
        float vw = clipf(fmaf(L1.y, chw, sb.y) - ob.y, -CLIPV, CLIPV);
        float ex = __expf(vx), ey = __expf(vy), ez = __expf(vz), ew = __expf(vw);
        a[j].x = fmaf(ex, S15, -S15);
        a[j].y = fmaf(ey, S15, -S15);
        a[j].z = fmaf(ez, S15, -S15);
        a[j].w = fmaf(ew, S15, -S15);
        B.x *= fmaf(ex, S15, S15);
        B.y *= fmaf(ey, S15, S15);
        B.z *= fmaf(ez, S15, S15);
        B.w *= fmaf(ew, S15, S15);
    }
    cn_tail(a, wfs, B, satl2, cwl2, oc, wp);
}

// ---------------- final: dec = llr_in + sum c2v, transposed out ------------
__global__ void k_out(const float* __restrict__ in, float* __restrict__ out,
                      int fb) {
    __shared__ float tile[BSZ * 33];
    const __half* cv = reinterpret_cast<const __half*>(g_c2v + fb * BUFU2);
    int n0 = blockIdx.x * 32;
    int t = threadIdx.x;
#pragma unroll
    for (int k = 0; k < 8; k++) {       // b-fast mapping: coalesced plane reads
        int idx = t + k * 256;
        int b = idx & 63, nn = idx >> 6;
        int n = n0 + nn;
        float s = ((__half2float(cv[0 * N_VN * BSZ + n * BSZ + b]) +
                    __half2float(cv[1 * N_VN * BSZ + n * BSZ + b])) +
                    __half2float(cv[2 * N_VN * BSZ + n * BSZ + b])) +
                    __half2float(cv[3 * N_VN * BSZ + n * BSZ + b]);
        tile[b * 33 + nn] = s;
    }
    __syncthreads();
#pragma unroll
    for (int k = 0; k < 8; k++) {       // n-fast mapping: coalesced out writes
        int idx = t + k * 256;
        int nn = idx & 31, b = idx >> 5;
        out[b * N_VN + n0 + nn] = in[b * N_VN + n0 + nn] + tile[b * 33 + nn];
    }
}

// ---------------- launch ----------------
extern "C" void kernel_launch(void* const* d_in, const int* in_sizes, int n_in,
                              void* d_out, int out_size) {
    const float* llr  = (const float*)d_in[0];
    const float* cn_w = (const float*)d_in[1];
    const float* ch_w = (const float*)d_in[2];
    const int*   e2v  = (const int*)d_in[3];
    int iters = in_sizes[1];   // cn_weight length

    k_setup<<<N_VN / 32, 256>>>(llr);
    k_build_inverse<<<(E_EDGES + 255) / 256, 256>>>(e2v);
    k_sort4<<<(N_VN + 255) / 256, 256>>>();

    k_cn0<<<(M_CN * 16) / 256, 256>>>(cn_w, ch_w);           // writes buf 1
    for (int it = 1; it < iters; it++)
        k_cn<<<(M_CN * 16) / 256, 256>>>(cn_w, ch_w, it, it & 1);

    k_out<<<N_VN / 32, 256>>>(llr, (float*)d_out, iters & 1);
}

// round 16
// speedup vs baseline: 1.6882x; 1.0606x over previous
#include <cuda_runtime.h>
#include <cuda_fp16.h>

#define N_VN    24576
#define D_V     4
#define D_C     8
#define E_EDGES (N_VN * D_V)     // 98304
#define M_CN    (E_EDGES / D_C)  // 12288
#define BSZ     64
#define CLIPV   20.0f
#define S15     3.0517578125e-05f   // 2^-15
#define S14     6.103515625e-05f    // 2^-14
#define LN2F    0.69314718056f

#define PLANEU2 (N_VN * 16)      // uint2 (=4 halves) elements per plane
#define BUFU2   (4 * PLANEU2)    // uint2 elements per buffer (4 slots)

// ---------------- scratch (device globals: allocation-free) ----------------
__device__ __half g_llrT[N_VN * BSZ];              // llr transposed [vn][b], fp16
__device__ uint2 g_c2v[2 * BUFU2];                 // double-buffered [buf][slot][vn][b/4]
__device__ int   g_vn_edges[N_VN * D_V];           // vn -> its 4 edges (sorted)
__device__ __align__(16) int2 g_eidx[E_EDGES];     // edge -> {vn*16, slot*PLANEU2+vn*16}
__device__ int   g_vn_cnt[N_VN];

__device__ __forceinline__ float clipf(float v, float lo, float hi) {
    return fminf(fmaxf(v, lo), hi);
}
__device__ __forceinline__ __half2 h2(unsigned u) {
    return *reinterpret_cast<__half2*>(&u);
}

// ------------- setup: transpose llr fp32 [b][n] -> fp16 [n][b] -------------
__global__ void k_setup(const float* __restrict__ in) {
    __shared__ float tile[BSZ * 33];
    int n0 = blockIdx.x * 32;
    int t = threadIdx.x;
#pragma unroll
    for (int k = 0; k < 8; k++) {       // load 32n x 64b tile (b-major source)
        int idx = t + k * 256;
        int nn = idx & 31, b = idx >> 5;
        tile[b * 33 + nn] = in[b * N_VN + n0 + nn];
    }
    if (t < 32) g_vn_cnt[n0 + t] = 0;
    __syncthreads();
#pragma unroll
    for (int k = 0; k < 8; k++) {
        int idx = t + k * 256;
        int b = idx & 63, nn = idx >> 6;
        g_llrT[(n0 + nn) * BSZ + b] = __float2half(tile[b * 33 + nn]);
    }
}

__global__ void k_build_inverse(const int* __restrict__ e2v) {
    int e = blockIdx.x * blockDim.x + threadIdx.x;
    if (e < E_EDGES) {
        int n = e2v[e];
        int pos = atomicAdd(&g_vn_cnt[n], 1);
        g_vn_edges[n * D_V + pos] = e;
    }
}

// sort each VN's 4 edges ascending (deterministic slots); emit index table
__global__ void k_sort4() {
    int n = blockIdx.x * blockDim.x + threadIdx.x;
    if (n >= N_VN) return;
    int* p = &g_vn_edges[n * 4];
    int a = p[0], b = p[1], c = p[2], d = p[3], x;
    if (a > b) { x = a; a = b; b = x; }
    if (c > d) { x = c; c = d; d = x; }
    if (a > c) { x = a; a = c; c = x; }
    if (b > d) { x = b; b = d; d = x; }
    if (b > c) { x = b; b = c; c = x; }
    p[0] = a; p[1] = b; p[2] = c; p[3] = d;
    int ro = n * 16;
    g_eidx[a] = make_int2(ro, 0 * PLANEU2 + ro);
    g_eidx[b] = make_int2(ro, 1 * PLANEU2 + ro);
    g_eidx[c] = make_int2(ro, 2 * PLANEU2 + ro);
    g_eidx[d] = make_int2(ro, 3 * PLANEU2 + ro);
}

// shared CN tail: from scaled tanh-numerators a[] and denominator product B,
// compute all 8 outputs and store to wp. Saturation by clamping C to
// +-oc*B BEFORE the logs: the clamped ratio evaluates to the reference's
// saturated value (EPS omission = 1e-6 relative, negligible).
__device__ __forceinline__ void cn_tail(float4* a, const int* wfs, float4 B,
                                        float cwl2, float oc, uint2* wp) {
    float4 ocB;
    ocB.x = oc * B.x; ocB.y = oc * B.y; ocB.z = oc * B.z; ocB.w = oc * B.w;
    float4 s[D_C];
    float4 S = make_float4(1.f, 1.f, 1.f, 1.f);
#pragma unroll
    for (int j = D_C - 1; j >= 0; j--) {
        s[j] = S;
        S.x *= a[j].x; S.y *= a[j].y; S.z *= a[j].z; S.w *= a[j].w;
    }
    float4 P = make_float4(1.f, 1.f, 1.f, 1.f);
#pragma unroll
    for (int j = 0; j < D_C; j++) {
        float bx = a[j].x + S14, by = a[j].y + S14;
        float bz = a[j].z + S14, bw = a[j].w + S14;
        float Cx = clipf((P.x * s[j].x) * bx, -ocB.x, ocB.x);
        float Cy = clipf((P.y * s[j].y) * by, -ocB.y, ocB.y);
        float Cz = clipf((P.z * s[j].z) * bz, -ocB.z, ocB.z);
        float Cw = clipf((P.w * s[j].w) * bw, -ocB.w, ocB.w);
        float dx = __log2f(B.x + Cx) - __log2f(B.x - Cx);
        float dy = __log2f(B.y + Cy) - __log2f(B.y - Cy);
        float dz = __log2f(B.z + Cz) - __log2f(B.z - Cz);
        float dw = __log2f(B.w + Cw) - __log2f(B.w - Cw);
        float cx = clipf(dx * cwl2, -CLIPV, CLIPV);
        float cy = clipf(dy * cwl2, -CLIPV, CLIPV);
        float cz = clipf(dz * cwl2, -CLIPV, CLIPV);
        float cv = clipf(dw * cwl2, -CLIPV, CLIPV);
        __half2 ha = __floats2half2_rn(cx, cy);
        __half2 hb = __floats2half2_rn(cz, cv);
        uint2 o;
        o.x = *reinterpret_cast<unsigned*>(&ha);
        o.y = *reinterpret_cast<unsigned*>(&hb);
        wp[wfs[j]] = o;
        P.x *= a[j].x; P.y *= a[j].y; P.z *= a[j].z; P.w *= a[j].w;
    }
}

// convert clipped v (2x half2) into scaled tanh numerators + denom product
__device__ __forceinline__ void edge_exp(__half2 vA, __half2 vB,
                                         float4* aj, float4* B) {
    float2 va = __half22float2(vA);
    float2 vb = __half22float2(vB);
    float ex = __expf(va.x), ey = __expf(va.y);
    float ez = __expf(vb.x), ew = __expf(vb.y);
    aj->x = fmaf(ex, S15, -S15);
    aj->y = fmaf(ey, S15, -S15);
    aj->z = fmaf(ez, S15, -S15);
    aj->w = fmaf(ew, S15, -S15);
    B->x *= fmaf(ex, S15, S15);
    B->y *= fmaf(ey, S15, S15);
    B->z *= fmaf(ez, S15, S15);
    B->w *= fmaf(ew, S15, S15);
}

// ------------- iteration 0: c2v == 0, no c2v reads at all ------------------
__global__ void __launch_bounds__(256, 2) k_cn0(const float* __restrict__ cn_w,
                                                const float* __restrict__ ch_w) {
    int idx = blockIdx.x * blockDim.x + threadIdx.x;   // M_CN * 16
    int cn = idx >> 4, qq = idx & 15;
    float cw  = __ldg(&cn_w[0]);
    float chw = __ldg(&ch_w[0]);
    const float oc = 0.999999f;
    float cwl2 = cw * LN2F;
    __half2 chw2 = __float2half2_rn(chw);
    __half2 hi = __float2half2_rn(CLIPV), lo = __float2half2_rn(-CLIPV);
    uint2* wp = g_c2v + BUFU2;          // write buffer 1
    const uint2* lp = reinterpret_cast<const uint2*>(g_llrT);

    const int4* ei4 = reinterpret_cast<const int4*>(g_eidx + cn * D_C);
    int4 e01 = __ldg(ei4 + 0);
    int4 e23 = __ldg(ei4 + 1);
    int4 e45 = __ldg(ei4 + 2);
    int4 e67 = __ldg(ei4 + 3);
    int ros[D_C] = {e01.x, e01.z, e23.x, e23.z, e45.x, e45.z, e67.x, e67.z};
    int wfs[D_C] = {e01.y, e01.w, e23.y, e23.w, e45.y, e45.w, e67.y, e67.w};

    float4 a[D_C];
    float4 B = make_float4(1.f, 1.f, 1.f, 1.f);
#pragma unroll
    for (int j = 0; j < D_C; j++) {
        int ro = ros[j] + qq;
        wfs[j] += qq;
        uint2 ul = lp[ro];
        __half2 vA = __hmin2(__hmax2(__hmul2(h2(ul.x), chw2), lo), hi);
        __half2 vB = __hmin2(__hmax2(__hmul2(h2(ul.y), chw2), lo), hi);
        edge_exp(vA, vB, &a[j], &B);
    }
    cn_tail(a, wfs, B, cwl2, oc, wp);
}

// ------------- main per-iteration kernel (it >= 1) -------------------------
// One thread = one CN x 4 batch lanes. Reads buffer rb, writes rb^1.
// v2c computed entirely in fp16 (inputs are fp16-quantized anyway).
__global__ void __launch_bounds__(256, 2) k_cn(const float* __restrict__ cn_w,
                                               const float* __restrict__ ch_w,
                                               int it, int rb) {
    int idx = blockIdx.x * blockDim.x + threadIdx.x;   // M_CN * 16
    int cn = idx >> 4, qq = idx & 15;
    float cw  = __ldg(&cn_w[it]);
    float chw = __ldg(&ch_w[it]);
    const float oc = 0.999999f;
    float cwl2 = cw * LN2F;
    __half2 chw2 = __float2half2_rn(chw);
    __half2 hi = __float2half2_rn(CLIPV), lo = __float2half2_rn(-CLIPV);
    const uint2* rp = g_c2v + rb * BUFU2;
    uint2*       wp = g_c2v + (rb ^ 1) * BUFU2;
    const uint2* lp = reinterpret_cast<const uint2*>(g_llrT);

    const int4* ei4 = reinterpret_cast<const int4*>(g_eidx + cn * D_C);
    int4 e01 = __ldg(ei4 + 0);
    int4 e23 = __ldg(ei4 + 1);
    int4 e45 = __ldg(ei4 + 2);
    int4 e67 = __ldg(ei4 + 3);
    int ros[D_C] = {e01.x, e01.z, e23.x, e23.z, e45.x, e45.z, e67.x, e67.z};
    int wfs[D_C] = {e01.y, e01.w, e23.y, e23.w, e45.y, e45.w, e67.y, e67.w};

    float4 a[D_C];
    float4 B = make_float4(1.f, 1.f, 1.f, 1.f);
#pragma unroll
    for (int j = 0; j < D_C; j++) {
        int ro = ros[j] + qq;
        int wf = wfs[j] + qq;
        wfs[j] = wf;
        uint2 u0 = rp[ro];
        uint2 u1 = rp[ro + PLANEU2];
        uint2 u2 = rp[ro + 2 * PLANEU2];
        uint2 u3 = rp[ro + 3 * PLANEU2];
        uint2 uo = rp[wf];                         // own c2v (no slot selects)
        uint2 ul = lp[ro];
        __half2 sA = __hadd2(__hadd2(h2(u0.x), h2(u1.x)), __hadd2(h2(u2.x), h2(u3.x)));
        __half2 sB = __hadd2(__hadd2(h2(u0.y), h2(u1.y)), __hadd2(h2(u2.y), h2(u3.y)));
        // v = clip(L*chw + sum - own), all fp16
        __half2 vA = __hsub2(__hfma2(h2(ul.x), chw2, sA), h2(uo.x));
        __half2 vB = __hsub2(__hfma2(h2(ul.y), chw2, sB), h2(uo.y));
        vA = __hmin2(__hmax2(vA, lo), hi);
        vB = __hmin2(__hmax2(vB, lo), hi);
        edge_exp(vA, vB, &a[j], &B);
    }
    cn_tail(a, wfs, B, cwl2, oc, wp);
}

// ---------------- final: dec = llr_in + sum c2v, transposed out ------------
__global__ void k_out(const float* __restrict__ in, float* __restrict__ out,
                      int fb) {
    __shared__ float tile[BSZ * 33];
    const __half* cv = reinterpret_cast<const __half*>(g_c2v + fb * BUFU2);
    int n0 = blockIdx.x * 32;
    int t = threadIdx.x;
#pragma unroll
    for (int k = 0; k < 8; k++) {       // b-fast mapping: coalesced plane reads
        int idx = t + k * 256;
        int b = idx & 63, nn = idx >> 6;
        int n = n0 + nn;
        float s = ((__half2float(cv[0 * N_VN * BSZ + n * BSZ + b]) +
                    __half2float(cv[1 * N_VN * BSZ + n * BSZ + b])) +
                    __half2float(cv[2 * N_VN * BSZ + n * BSZ + b])) +
                    __half2float(cv[3 * N_VN * BSZ + n * BSZ + b]);
        tile[b * 33 + nn] = s;
    }
    __syncthreads();
#pragma unroll
    for (int k = 0; k < 8; k++) {       // n-fast mapping: coalesced out writes
        int idx = t + k * 256;
        int nn = idx & 31, b = idx >> 5;
        out[b * N_VN + n0 + nn] = in[b * N_VN + n0 + nn] + tile[b * 33 + nn];
    }
}

// ---------------- launch ----------------
extern "C" void kernel_launch(void* const* d_in, const int* in_sizes, int n_in,
                              void* d_out, int out_size) {
    const float* llr  = (const float*)d_in[0];
    const float* cn_w = (const float*)d_in[1];
    const float* ch_w = (const float*)d_in[2];
    const int*   e2v  = (const int*)d_in[3];
    int iters = in_sizes[1];   // cn_weight length

    k_setup<<<N_VN / 32, 256>>>(llr);
    k_build_inverse<<<(E_EDGES + 255) / 256, 256>>>(e2v);
    k_sort4<<<(N_VN + 255) / 256, 256>>>();

    k_cn0<<<(M_CN * 16) / 256, 256>>>(cn_w, ch_w);           // writes buf 1
    for (int it = 1; it < iters; it++)
        k_cn<<<(M_CN * 16) / 256, 256>>>(cn_w, ch_w, it, it & 1);

    k_out<<<N_VN / 32, 256>>>(llr, (float*)d_out, iters & 1);
}

// round 17
// speedup vs baseline: 1.7945x; 1.0630x over previous
#include <cuda_runtime.h>
#include <cuda_fp16.h>

#define N_VN    24576
#define D_V     4
#define D_C     8
#define E_EDGES (N_VN * D_V)     // 98304
#define M_CN    (E_EDGES / D_C)  // 12288
#define BSZ     64
#define S15     3.0517578125e-05f   // 2^-15
#define S14     6.103515625e-05f    // 2^-14
#define LN2F    0.69314718056f
#define LOG2E   1.44269504089f
#define SCLIP   28.8539008178f      // 20 * log2(e): clip bound in log2 domain

#define PLANEU2 (N_VN * 16)      // uint2 (=4 halves) elements per plane
#define BUFU2   (4 * PLANEU2)    // uint2 elements per buffer (4 slots)

// Messages are stored SCALED BY LOG2E (log2-domain LLRs): exp(v) becomes a
// bare ex2, and the CN output scale ln2*log2e cancels to exactly cn_weight.

// ---------------- scratch (device globals: allocation-free) ----------------
__device__ __half g_llrT[N_VN * BSZ];              // llr*log2e transposed [vn][b]
__device__ uint2 g_c2v[2 * BUFU2];                 // double-buffered [buf][slot][vn][b/4]
__device__ int   g_vn_edges[N_VN * D_V];           // vn -> its 4 edges (sorted)
__device__ __align__(16) int2 g_eidx[E_EDGES];     // edge -> {vn*16, slot*PLANEU2+vn*16}
__device__ int   g_vn_cnt[N_VN];

__device__ __forceinline__ float clipf(float v, float lo, float hi) {
    return fminf(fmaxf(v, lo), hi);
}
__device__ __forceinline__ __half2 h2(unsigned u) {
    return *reinterpret_cast<__half2*>(&u);
}
__device__ __forceinline__ float ex2f(float x) {
    float y;
    asm("ex2.approx.f32 %0, %1;" : "=f"(y) : "f"(x));
    return y;
}

// ------------- setup: transpose llr fp32 [b][n] -> fp16 [n][b] * log2e -----
__global__ void k_setup(const float* __restrict__ in) {
    __shared__ float tile[BSZ * 33];
    int n0 = blockIdx.x * 32;
    int t = threadIdx.x;
#pragma unroll
    for (int k = 0; k < 8; k++) {       // load 32n x 64b tile (b-major source)
        int idx = t + k * 256;
        int nn = idx & 31, b = idx >> 5;
        tile[b * 33 + nn] = in[b * N_VN + n0 + nn];
    }
    if (t < 32) g_vn_cnt[n0 + t] = 0;
    __syncthreads();
#pragma unroll
    for (int k = 0; k < 8; k++) {
        int idx = t + k * 256;
        int b = idx & 63, nn = idx >> 6;
        g_llrT[(n0 + nn) * BSZ + b] = __float2half(tile[b * 33 + nn] * LOG2E);
    }
}

__global__ void k_build_inverse(const int* __restrict__ e2v) {
    int e = blockIdx.x * blockDim.x + threadIdx.x;
    if (e < E_EDGES) {
        int n = e2v[e];
        int pos = atomicAdd(&g_vn_cnt[n], 1);
        g_vn_edges[n * D_V + pos] = e;
    }
}

// sort each VN's 4 edges ascending (deterministic slots); emit index table
__global__ void k_sort4() {
    int n = blockIdx.x * blockDim.x + threadIdx.x;
    if (n >= N_VN) return;
    int* p = &g_vn_edges[n * 4];
    int a = p[0], b = p[1], c = p[2], d = p[3], x;
    if (a > b) { x = a; a = b; b = x; }
    if (c > d) { x = c; c = d; d = x; }
    if (a > c) { x = a; a = c; c = x; }
    if (b > d) { x = b; b = d; d = x; }
    if (b > c) { x = b; b = c; c = x; }
    p[0] = a; p[1] = b; p[2] = c; p[3] = d;
    int ro = n * 16;
    g_eidx[a] = make_int2(ro, 0 * PLANEU2 + ro);
    g_eidx[b] = make_int2(ro, 1 * PLANEU2 + ro);
    g_eidx[c] = make_int2(ro, 2 * PLANEU2 + ro);
    g_eidx[d] = make_int2(ro, 3 * PLANEU2 + ro);
}

// CN tail: a[] = scaled tanh numerators, B = denominator product.
//   d = log2(B+C) - log2(B-C)  (B +- C > 0 always: |a_i| <= b_i, equality
//   only in the all-saturated case, where log2(0) = -inf -> d = +-inf and
//   the satl2 clamp below yields exactly the reference's saturated value)
//   c' = clip(d, +-satl2) * cw   (output already in log2-scaled domain)
__device__ __forceinline__ void cn_tail(float4* a, const int* wfs, float4 B,
                                        float cw, float satl2, bool need2,
                                        uint2* wp) {
    float4 s[D_C];
    float4 S = make_float4(1.f, 1.f, 1.f, 1.f);
#pragma unroll
    for (int j = D_C - 1; j >= 0; j--) {
        s[j] = S;
        S.x *= a[j].x; S.y *= a[j].y; S.z *= a[j].z; S.w *= a[j].w;
    }
    float4 P = make_float4(1.f, 1.f, 1.f, 1.f);
#pragma unroll
    for (int j = 0; j < D_C; j++) {
        float bx = a[j].x + S14, by = a[j].y + S14;
        float bz = a[j].z + S14, bw = a[j].w + S14;
        float Cx = (P.x * s[j].x) * bx;
        float Cy = (P.y * s[j].y) * by;
        float Cz = (P.z * s[j].z) * bz;
        float Cw = (P.w * s[j].w) * bw;
        float dx = __log2f(B.x + Cx) - __log2f(B.x - Cx);
        float dy = __log2f(B.y + Cy) - __log2f(B.y - Cy);
        float dz = __log2f(B.z + Cz) - __log2f(B.z - Cz);
        float dw = __log2f(B.w + Cw) - __log2f(B.w - Cw);
        float cx = clipf(dx, -satl2, satl2) * cw;
        float cy = clipf(dy, -satl2, satl2) * cw;
        float cz = clipf(dz, -satl2, satl2) * cw;
        float cv = clipf(dw, -satl2, satl2) * cw;
        if (need2) {                    // uniform: only when satl2*|cw|>SCLIP
            cx = clipf(cx, -SCLIP, SCLIP);
            cy = clipf(cy, -SCLIP, SCLIP);
            cz = clipf(cz, -SCLIP, SCLIP);
            cv = clipf(cv, -SCLIP, SCLIP);
        }
        __half2 ha = __floats2half2_rn(cx, cy);
        __half2 hb = __floats2half2_rn(cz, cv);
        uint2 o;
        o.x = *reinterpret_cast<unsigned*>(&ha);
        o.y = *reinterpret_cast<unsigned*>(&hb);
        wp[wfs[j]] = o;
        P.x *= a[j].x; P.y *= a[j].y; P.z *= a[j].z; P.w *= a[j].w;
    }
}

// convert clipped scaled-v (2x half2) into tanh numerators + denom product
__device__ __forceinline__ void edge_exp(__half2 vA, __half2 vB,
                                         float4* aj, float4* B) {
    float2 va = __half22float2(vA);
    float2 vb = __half22float2(vB);
    float ex = ex2f(va.x), ey = ex2f(va.y);
    float ez = ex2f(vb.x), ew = ex2f(vb.y);
    aj->x = fmaf(ex, S15, -S15);
    aj->y = fmaf(ey, S15, -S15);
    aj->z = fmaf(ez, S15, -S15);
    aj->w = fmaf(ew, S15, -S15);
    B->x *= fmaf(ex, S15, S15);
    B->y *= fmaf(ey, S15, S15);
    B->z *= fmaf(ez, S15, S15);
    B->w *= fmaf(ew, S15, S15);
}

// ------------- iteration 0: c2v == 0, no c2v reads at all ------------------
__global__ void __launch_bounds__(256, 2) k_cn0(const float* __restrict__ cn_w,
                                                const float* __restrict__ ch_w) {
    int idx = blockIdx.x * blockDim.x + threadIdx.x;   // M_CN * 16
    int cn = idx >> 4, qq = idx & 15;
    float cw  = __ldg(&cn_w[0]);
    float chw = __ldg(&ch_w[0]);
    float satl2 = __log2f((1.0f + 0.999999f) / (1.0f - 0.999999f + 1e-12f));
    bool need2 = satl2 * fabsf(cw) > SCLIP;
    __half2 chw2 = __float2half2_rn(chw);              // llrT already *log2e
    __half2 hi = __float2half2_rn(SCLIP), lo = __float2half2_rn(-SCLIP);
    uint2* wp = g_c2v + BUFU2;          // write buffer 1
    const uint2* lp = reinterpret_cast<const uint2*>(g_llrT);

    const int4* ei4 = reinterpret_cast<const int4*>(g_eidx + cn * D_C);
    int4 e01 = __ldg(ei4 + 0);
    int4 e23 = __ldg(ei4 + 1);
    int4 e45 = __ldg(ei4 + 2);
    int4 e67 = __ldg(ei4 + 3);
    int ros[D_C] = {e01.x, e01.z, e23.x, e23.z, e45.x, e45.z, e67.x, e67.z};
    int wfs[D_C] = {e01.y, e01.w, e23.y, e23.w, e45.y, e45.w, e67.y, e67.w};

    float4 a[D_C];
    float4 B = make_float4(1.f, 1.f, 1.f, 1.f);
#pragma unroll
    for (int j = 0; j < D_C; j++) {
        int ro = ros[j] + qq;
        wfs[j] += qq;
        uint2 ul = lp[ro];
        __half2 vA = __hmin2(__hmax2(__hmul2(h2(ul.x), chw2), lo), hi);
        __half2 vB = __hmin2(__hmax2(__hmul2(h2(ul.y), chw2), lo), hi);
        edge_exp(vA, vB, &a[j], &B);
    }
    cn_tail(a, wfs, B, cw, satl2, need2, wp);
}

// ------------- main per-iteration kernel (it >= 1) -------------------------
// One thread = one CN x 4 batch lanes. Reads buffer rb, writes rb^1.
__global__ void __launch_bounds__(256, 2) k_cn(const float* __restrict__ cn_w,
                                               const float* __restrict__ ch_w,
                                               int it, int rb) {
    int idx = blockIdx.x * blockDim.x + threadIdx.x;   // M_CN * 16
    int cn = idx >> 4, qq = idx & 15;
    float cw  = __ldg(&cn_w[it]);
    float chw = __ldg(&ch_w[it]);
    float satl2 = __log2f((1.0f + 0.999999f) / (1.0f - 0.999999f + 1e-12f));
    bool need2 = satl2 * fabsf(cw) > SCLIP;
    __half2 chw2 = __float2half2_rn(chw);
    __half2 hi = __float2half2_rn(SCLIP), lo = __float2half2_rn(-SCLIP);
    const uint2* rp = g_c2v + rb * BUFU2;
    uint2*       wp = g_c2v + (rb ^ 1) * BUFU2;
    const uint2* lp = reinterpret_cast<const uint2*>(g_llrT);

    const int4* ei4 = reinterpret_cast<const int4*>(g_eidx + cn * D_C);
    int4 e01 = __ldg(ei4 + 0);
    int4 e23 = __ldg(ei4 + 1);
    int4 e45 = __ldg(ei4 + 2);
    int4 e67 = __ldg(ei4 + 3);
    int ros[D_C] = {e01.x, e01.z, e23.x, e23.z, e45.x, e45.z, e67.x, e67.z};
    int wfs[D_C] = {e01.y, e01.w, e23.y, e23.w, e45.y, e45.w, e67.y, e67.w};

    float4 a[D_C];
    float4 B = make_float4(1.f, 1.f, 1.f, 1.f);
#pragma unroll
    for (int j = 0; j < D_C; j++) {
        int ro = ros[j] + qq;
        int wf = wfs[j] + qq;
        wfs[j] = wf;
        uint2 u0 = rp[ro];
        uint2 u1 = rp[ro + PLANEU2];
        uint2 u2 = rp[ro + 2 * PLANEU2];
        uint2 u3 = rp[ro + 3 * PLANEU2];
        uint2 uo = rp[wf];                         // own c2v (no slot selects)
        uint2 ul = lp[ro];
        __half2 sA = __hadd2(__hadd2(h2(u0.x), h2(u1.x)), __hadd2(h2(u2.x), h2(u3.x)));
        __half2 sB = __hadd2(__hadd2(h2(u0.y), h2(u1.y)), __hadd2(h2(u2.y), h2(u3.y)));
        // v' = clip(L'*chw + sum' - own'), all fp16, log2-scaled domain
        __half2 vA = __hsub2(__hfma2(h2(ul.x), chw2, sA), h2(uo.x));
        __half2 vB = __hsub2(__hfma2(h2(ul.y), chw2, sB), h2(uo.y));
        vA = __hmin2(__hmax2(vA, lo), hi);
        vB = __hmin2(__hmax2(vB, lo), hi);
        edge_exp(vA, vB, &a[j], &B);
    }
    cn_tail(a, wfs, B, cw, satl2, need2, wp);
}

// -------- final: dec = llr_in + (sum c2v')*ln2, transposed out -------------
__global__ void k_out(const float* __restrict__ in, float* __restrict__ out,
                      int fb) {
    __shared__ float tile[BSZ * 33];
    const __half* cv = reinterpret_cast<const __half*>(g_c2v + fb * BUFU2);
    int n0 = blockIdx.x * 32;
    int t = threadIdx.x;
#pragma unroll
    for (int k = 0; k < 8; k++) {       // b-fast mapping: coalesced plane reads
        int idx = t + k * 256;
        int b = idx & 63, nn = idx >> 6;
        int n = n0 + nn;
        float s = ((__half2float(cv[0 * N_VN * BSZ + n * BSZ + b]) +
                    __half2float(cv[1 * N_VN * BSZ + n * BSZ + b])) +
                    __half2float(cv[2 * N_VN * BSZ + n * BSZ + b])) +
                    __half2float(cv[3 * N_VN * BSZ + n * BSZ + b]);
        tile[b * 33 + nn] = s;
    }
    __syncthreads();
#pragma unroll
    for (int k = 0; k < 8; k++) {       // n-fast mapping: coalesced out writes
        int idx = t + k * 256;
        int nn = idx & 31, b = idx >> 5;
        out[b * N_VN + n0 + nn] =
            fmaf(tile[b * 33 + nn], LN2F, in[b * N_VN + n0 + nn]);
    }
}

// ---------------- launch ----------------
extern "C" void kernel_launch(void* const* d_in, const int* in_sizes, int n_in,
                              void* d_out, int out_size) {
    const float* llr  = (const float*)d_in[0];
    const float* cn_w = (const float*)d_in[1];
    const float* ch_w = (const float*)d_in[2];
    const int*   e2v  = (const int*)d_in[3];
    int iters = in_sizes[1];   // cn_weight length

    k_setup<<<N_VN / 32, 256>>>(llr);
    k_build_inverse<<<(E_EDGES + 255) / 256, 256>>>(e2v);
    k_sort4<<<(N_VN + 255) / 256, 256>>>();

    k_cn0<<<(M_CN * 16) / 256, 256>>>(cn_w, ch_w);           // writes buf 1
    for (int it = 1; it < iters; it++)
        k_cn<<<(M_CN * 16) / 256, 256>>>(cn_w, ch_w, it, it & 1);

    k_out<<<N_VN / 32, 256>>>(llr, (float*)d_out, iters & 1);
}